// round 14
// baseline (speedup 1.0000x reference)
#include <cuda_runtime.h>
#include <cuda_bf16.h>
#include <math.h>
#include <stdint.h>

#define BB   4
#define NN_  1024
#define DD   1024
#define HH   16
#define HDD  64
#define TDD  768
#define TLL  77
#define MTOK (BB*NN_)       // 4096

// ---------------- scratch (zero-initialized device globals) ----------------
__device__ float g_mod[BB*6*DD];
__device__ float g_h[MTOK*DD];
__device__ float g_qkv[MTOK*3*DD];
__device__ float g_attn[MTOK*DD];
__device__ float g_x1[MTOK*DD];
__device__ float g_x2[MTOK*DD];
__device__ float g_ctx[512*DD];          // 308 valid rows, rest stays 0
__device__ float g_q[MTOK*DD];
__device__ float g_k[512*DD];            // pad rows stay 0
__device__ float g_v[512*DD];            // pad rows stay 0
__device__ float g_S[64ull*1024*1024];   // score scratch
__device__ float g_hidden[(size_t)MTOK*4*DD];

// transposed weights [N, K] row-major
__device__ float g_Wt_qkv [3072u*1024u];
__device__ float g_Wt_proj[1024u*1024u];
__device__ float g_Wt_q   [1024u*1024u];
__device__ float g_Wt_k   [1024u*1024u];
__device__ float g_Wt_v   [1024u*1024u];
__device__ float g_Wt_out [1024u*1024u];
__device__ float g_Wt_fc1 [4096u*1024u];
__device__ float g_Wt_fc2 [4096u*1024u];
__device__ float g_Wt_ctx [1024u*768u];

__device__ __forceinline__ float gelu_tanh(float x) {
    float inner = 0.7978845608028654f * (x + 0.044715f * x * x * x);
    return 0.5f * x * (1.0f + tanhf(inner));
}

__device__ __forceinline__ uint32_t smem_u32(const void* p) {
    uint32_t a;
    asm("{ .reg .u64 t; cvta.to.shared.u64 t, %1; cvt.u32.u64 %0, t; }"
        : "=r"(a) : "l"(p));
    return a;
}

// ---------------- weight transpose: out[n*K+k] = in[k*N+n] ------------------
__global__ __launch_bounds__(256) void transpose_kernel(
    const float* __restrict__ in, float* __restrict__ outp, int K, int N)
{
    __shared__ float t[32][33];
    int n0 = blockIdx.x * 32, k0 = blockIdx.y * 32;
    int x = threadIdx.x, y = threadIdx.y;   // block (32, 8)
    #pragma unroll
    for (int i = 0; i < 32; i += 8)
        t[y + i][x] = in[(size_t)(k0 + y + i) * N + n0 + x];
    __syncthreads();
    #pragma unroll
    for (int i = 0; i < 32; i += 8)
        outp[(size_t)(n0 + y + i) * K + k0 + x] = t[x][y + i];
}

// ---------------- adaLN: mod = silu(c) @ W_ada + b_ada  [4, 6144] ----------
__global__ __launch_bounds__(256) void ada_kernel(
    const float* __restrict__ c, const float* __restrict__ W,
    const float* __restrict__ bias, float* __restrict__ mod)
{
    __shared__ float sc[BB][DD];
    int tid = threadIdx.x;
    for (int i = tid; i < BB*DD; i += 256) {
        float v = c[i];
        sc[i >> 10][i & 1023] = v / (1.0f + expf(-v));
    }
    __syncthreads();
    int col = blockIdx.x * 256 + tid;
    float a0 = 0.f, a1 = 0.f, a2 = 0.f, a3 = 0.f;
    #pragma unroll 4
    for (int k = 0; k < DD; k++) {
        float w = W[(size_t)k * (6*DD) + col];
        a0 += w * sc[0][k];
        a1 += w * sc[1][k];
        a2 += w * sc[2][k];
        a3 += w * sc[3][k];
    }
    float bb = bias[col];
    mod[0*(size_t)(6*DD) + col] = a0 + bb;
    mod[1*(size_t)(6*DD) + col] = a1 + bb;
    mod[2*(size_t)(6*DD) + col] = a2 + bb;
    mod[3*(size_t)(6*DD) + col] = a3 + bb;
}

// ---------------- LayerNorm + modulate -------------------------------------
__global__ __launch_bounds__(256) void ln_mod_kernel(
    const float* __restrict__ X, const float* __restrict__ mod,
    float* __restrict__ Y, int shiftChunk)
{
    __shared__ float red[2][8];
    int row = blockIdx.x;
    int b = row >> 10;
    int tid = threadIdx.x;
    const float4* xr = (const float4*)(X + (size_t)row * DD);
    float4 xv = xr[tid];
    float s  = xv.x + xv.y + xv.z + xv.w;
    float ss = xv.x*xv.x + xv.y*xv.y + xv.z*xv.z + xv.w*xv.w;
    #pragma unroll
    for (int o = 16; o; o >>= 1) {
        s  += __shfl_xor_sync(0xffffffffu, s,  o);
        ss += __shfl_xor_sync(0xffffffffu, ss, o);
    }
    if ((tid & 31) == 0) { red[0][tid >> 5] = s; red[1][tid >> 5] = ss; }
    __syncthreads();
    float ts = 0.f, tss = 0.f;
    #pragma unroll
    for (int i = 0; i < 8; i++) { ts += red[0][i]; tss += red[1][i]; }
    float mean = ts * (1.0f / (float)DD);
    float var  = tss * (1.0f / (float)DD) - mean * mean;
    float rstd = rsqrtf(var + 1e-6f);
    const float4* shp = (const float4*)(mod + (size_t)b*6*DD + (size_t)shiftChunk*DD);
    const float4* scp = (const float4*)(mod + (size_t)b*6*DD + (size_t)(shiftChunk+1)*DD);
    float4 sh4 = shp[tid];
    float4 sc4 = scp[tid];
    float4 y;
    y.x = (xv.x - mean) * rstd * (1.0f + sc4.x) + sh4.x;
    y.y = (xv.y - mean) * rstd * (1.0f + sc4.y) + sh4.y;
    y.z = (xv.z - mean) * rstd * (1.0f + sc4.z) + sh4.z;
    y.w = (xv.w - mean) * rstd * (1.0f + sc4.w) + sh4.w;
    ((float4*)(Y + (size_t)row * DD))[tid] = y;
}

// ======================= mma.sync split-bf16 common =========================

__device__ __forceinline__ void ldsm_x4(
    uint32_t& r0, uint32_t& r1, uint32_t& r2, uint32_t& r3, uint32_t addr)
{
    asm volatile("ldmatrix.sync.aligned.m8n8.x4.shared.b16 {%0,%1,%2,%3}, [%4];"
                 : "=r"(r0), "=r"(r1), "=r"(r2), "=r"(r3) : "r"(addr));
}
__device__ __forceinline__ void ldsm_x2(uint32_t& r0, uint32_t& r1, uint32_t addr)
{
    asm volatile("ldmatrix.sync.aligned.m8n8.x2.shared.b16 {%0,%1}, [%2];"
                 : "=r"(r0), "=r"(r1) : "r"(addr));
}
__device__ __forceinline__ void mma16816(
    float* c, const uint32_t* a, const uint32_t* b)
{
    asm volatile(
        "mma.sync.aligned.m16n8k16.row.col.f32.bf16.bf16.f32 "
        "{%0,%1,%2,%3}, {%4,%5,%6,%7}, {%8,%9}, {%0,%1,%2,%3};"
        : "+f"(c[0]), "+f"(c[1]), "+f"(c[2]), "+f"(c[3])
        : "r"(a[0]), "r"(a[1]), "r"(a[2]), "r"(a[3]), "r"(b[0]), "r"(b[1]));
}

#define SPAD 40   // bf16 elements per smem row (32 data + 8 pad)

__device__ __forceinline__ void split4(float4 v, uint32_t& h0, uint32_t& h1,
                                       uint32_t& l0, uint32_t& l1)
{
    __nv_bfloat16 a = __float2bfloat16_rn(v.x);
    __nv_bfloat16 b = __float2bfloat16_rn(v.y);
    __nv_bfloat16 c = __float2bfloat16_rn(v.z);
    __nv_bfloat16 d = __float2bfloat16_rn(v.w);
    h0 = ((uint32_t)__bfloat16_as_ushort(b) << 16) | __bfloat16_as_ushort(a);
    h1 = ((uint32_t)__bfloat16_as_ushort(d) << 16) | __bfloat16_as_ushort(c);
    __nv_bfloat16 e = __float2bfloat16_rn(v.x - __bfloat162float(a));
    __nv_bfloat16 f = __float2bfloat16_rn(v.y - __bfloat162float(b));
    __nv_bfloat16 g = __float2bfloat16_rn(v.z - __bfloat162float(c));
    __nv_bfloat16 h = __float2bfloat16_rn(v.w - __bfloat162float(d));
    l0 = ((uint32_t)__bfloat16_as_ushort(f) << 16) | __bfloat16_as_ushort(e);
    l1 = ((uint32_t)__bfloat16_as_ushort(h) << 16) | __bfloat16_as_ushort(g);
}

// ======================= split-bf16 GEMM (linear layers) ====================
// (256, 2): 2 CTAs/SM (measured R13 win). Register prefetch of next K-chunk
// overlaps global-load latency with the mma compute phase.
template<bool HAS_BIAS, bool DO_GELU, bool HAS_RES>
__global__ __launch_bounds__(256, 2) void mgemm_kernel(
    const float* __restrict__ A, const float* __restrict__ Bt,
    const float* __restrict__ bias, const float* __restrict__ res,
    float* __restrict__ C, int M, int Nn, int K)
{
    __shared__ __nv_bfloat16 sA[2][128][SPAD];
    __shared__ __nv_bfloat16 sB[2][128][SPAD];

    int tid = threadIdx.x;
    int wid = tid >> 5, lane = tid & 31;
    int wm = (wid & 1) * 64;
    int wn = (wid >> 1) * 32;
    int m0 = blockIdx.y * 128;
    int n0 = blockIdx.x * 128;

    float acc[4][4][4];
    #pragma unroll
    for (int i = 0; i < 4; i++)
        #pragma unroll
        for (int j = 0; j < 4; j++)
            #pragma unroll
            for (int cc = 0; cc < 4; cc++) acc[i][j][cc] = 0.f;

    uint32_t aBase[2], bBase[2];
    {
        int arow = wm + (lane & 15);
        int acol = (lane >> 4) * 8;
        aBase[0] = smem_u32(&sA[0][arow][acol]);
        aBase[1] = smem_u32(&sA[1][arow][acol]);
        int brow = wn + (lane & 7);
        int bcol = ((lane >> 3) & 1) * 8;
        bBase[0] = smem_u32(&sB[0][brow][bcol]);
        bBase[1] = smem_u32(&sB[1][brow][bcol]);
    }

    int lr = tid >> 3;
    int lc = (tid & 7) * 4;
    bool aValid = (m0 + lr < M);   // same rows every chunk (lr, lr+32, ...)

    int nkt = K >> 5;
    float4 pa[4], pb[4];
    // ---- prologue: load chunk 0 ----
    {
        const float* Ab = A + (size_t)m0 * K;
        const float* Bb = Bt + (size_t)n0 * K;
        #pragma unroll
        for (int i = 0; i < 4; i++) {
            int row = lr + i*32;
            pa[i] = (m0 + row < M) ? *(const float4*)(Ab + (size_t)row*K + lc)
                                   : make_float4(0.f, 0.f, 0.f, 0.f);
            pb[i] = *(const float4*)(Bb + (size_t)row*K + lc);
        }
    }

    for (int kt = 0; kt < nkt; kt++) {
        // ---- split + store current chunk ----
        #pragma unroll
        for (int i = 0; i < 4; i++) {
            int row = lr + i*32;
            uint32_t h0, h1, l0, l1;
            split4(pa[i], h0, h1, l0, l1);
            *(uint2*)&sA[0][row][lc] = make_uint2(h0, h1);
            *(uint2*)&sA[1][row][lc] = make_uint2(l0, l1);
            split4(pb[i], h0, h1, l0, l1);
            *(uint2*)&sB[0][row][lc] = make_uint2(h0, h1);
            *(uint2*)&sB[1][row][lc] = make_uint2(l0, l1);
        }
        __syncthreads();

        // ---- prefetch next chunk (LDGs overlap mma below) ----
        if (kt + 1 < nkt) {
            const float* Ab = A + (size_t)m0 * K + (kt+1)*32;
            const float* Bb = Bt + (size_t)n0 * K + (kt+1)*32;
            #pragma unroll
            for (int i = 0; i < 4; i++) {
                int row = lr + i*32;
                pa[i] = ((i == 0) ? aValid : (m0 + row < M))
                        ? *(const float4*)(Ab + (size_t)row*K + lc)
                        : make_float4(0.f, 0.f, 0.f, 0.f);
                pb[i] = *(const float4*)(Bb + (size_t)row*K + lc);
            }
        }

        // ---- compute ----
        #pragma unroll
        for (int k16 = 0; k16 < 2; k16++) {
            uint32_t af[2][4][4], bf[2][4][2];
            #pragma unroll
            for (int p = 0; p < 2; p++) {
                #pragma unroll
                for (int mt = 0; mt < 4; mt++)
                    ldsm_x4(af[p][mt][0], af[p][mt][1], af[p][mt][2], af[p][mt][3],
                            aBase[p] + (uint32_t)(mt*16*SPAD + k16*16) * 2);
                #pragma unroll
                for (int nt = 0; nt < 4; nt++)
                    ldsm_x2(bf[p][nt][0], bf[p][nt][1],
                            bBase[p] + (uint32_t)(nt*8*SPAD + k16*16) * 2);
            }
            #pragma unroll
            for (int mt = 0; mt < 4; mt++)
                #pragma unroll
                for (int nt = 0; nt < 4; nt++) {
                    mma16816(acc[mt][nt], af[0][mt], bf[0][nt]);
                    mma16816(acc[mt][nt], af[0][mt], bf[1][nt]);
                    mma16816(acc[mt][nt], af[1][mt], bf[0][nt]);
                }
        }
        __syncthreads();
    }

    int gid = lane >> 2, tig = lane & 3;
    #pragma unroll
    for (int mt = 0; mt < 4; mt++) {
        #pragma unroll
        for (int nt = 0; nt < 4; nt++) {
            int col = n0 + wn + nt*8 + tig*2;
            float bx = 0.f, by = 0.f;
            if (HAS_BIAS) { bx = bias[col]; by = bias[col+1]; }
            #pragma unroll
            for (int half = 0; half < 2; half++) {
                int row = m0 + wm + mt*16 + gid + half*8;
                if (row < M) {
                    float vx = acc[mt][nt][half*2+0];
                    float vy = acc[mt][nt][half*2+1];
                    if (HAS_BIAS) { vx += bx; vy += by; }
                    if (DO_GELU)  { vx = gelu_tanh(vx); vy = gelu_tanh(vy); }
                    if (HAS_RES) {
                        float2 r2 = *(const float2*)(res + (size_t)row*Nn + col);
                        vx += r2.x; vy += r2.y;
                    }
                    *(float2*)(C + (size_t)row*Nn + col) = make_float2(vx, vy);
                }
            }
        }
    }
}

// ================= tensor attention scores: S = scale*Q@K^T =================
__global__ __launch_bounds__(256) void attn_s_mma(
    const float* __restrict__ Q, int ldq, int qRows,
    const float* __restrict__ Kp, int ldk, int kRows,
    float* __restrict__ S, int ldS, int Lk, float scale)
{
    __shared__ __nv_bfloat16 sA[2][128][SPAD];
    __shared__ __nv_bfloat16 sB[2][128][SPAD];

    int bh = blockIdx.z, b = bh >> 4, h = bh & 15;
    int i0 = blockIdx.y * 128;
    int j0 = blockIdx.x * 128;
    const float* Qb = Q  + (size_t)(b * qRows + i0) * ldq + h * HDD;
    const float* Kb = Kp + (size_t)(b * kRows + j0) * ldk + h * HDD;

    int tid = threadIdx.x;
    int wid = tid >> 5, lane = tid & 31;
    int wm = (wid & 1) * 64;
    int wn = (wid >> 1) * 32;

    float acc[4][4][4];
    #pragma unroll
    for (int i = 0; i < 4; i++)
        #pragma unroll
        for (int j = 0; j < 4; j++)
            #pragma unroll
            for (int cc = 0; cc < 4; cc++) acc[i][j][cc] = 0.f;

    uint32_t aBase[2], bBase[2];
    {
        int arow = wm + (lane & 15);
        int acol = (lane >> 4) * 8;
        aBase[0] = smem_u32(&sA[0][arow][acol]);
        aBase[1] = smem_u32(&sA[1][arow][acol]);
        int brow = wn + (lane & 7);
        int bcol = ((lane >> 3) & 1) * 8;
        bBase[0] = smem_u32(&sB[0][brow][bcol]);
        bBase[1] = smem_u32(&sB[1][brow][bcol]);
    }

    int lr = tid >> 3;
    int lc = (tid & 7) * 4;

    #pragma unroll
    for (int kt = 0; kt < 2; kt++) {     // K = HDD = 64
        #pragma unroll
        for (int i = 0; i < 4; i++) {
            int row = lr + i*32;
            float4 va = *(const float4*)(Qb + (size_t)row*ldq + kt*32 + lc);
            uint32_t h0, h1, l0, l1;
            split4(va, h0, h1, l0, l1);
            *(uint2*)&sA[0][row][lc] = make_uint2(h0, h1);
            *(uint2*)&sA[1][row][lc] = make_uint2(l0, l1);
            float4 vb = *(const float4*)(Kb + (size_t)row*ldk + kt*32 + lc);
            split4(vb, h0, h1, l0, l1);
            *(uint2*)&sB[0][row][lc] = make_uint2(h0, h1);
            *(uint2*)&sB[1][row][lc] = make_uint2(l0, l1);
        }
        __syncthreads();

        #pragma unroll
        for (int k16 = 0; k16 < 2; k16++) {
            uint32_t af[2][4][4], bf[2][4][2];
            #pragma unroll
            for (int p = 0; p < 2; p++) {
                #pragma unroll
                for (int mt = 0; mt < 4; mt++)
                    ldsm_x4(af[p][mt][0], af[p][mt][1], af[p][mt][2], af[p][mt][3],
                            aBase[p] + (uint32_t)(mt*16*SPAD + k16*16) * 2);
                #pragma unroll
                for (int nt = 0; nt < 4; nt++)
                    ldsm_x2(bf[p][nt][0], bf[p][nt][1],
                            bBase[p] + (uint32_t)(nt*8*SPAD + k16*16) * 2);
            }
            #pragma unroll
            for (int mt = 0; mt < 4; mt++)
                #pragma unroll
                for (int nt = 0; nt < 4; nt++) {
                    mma16816(acc[mt][nt], af[0][mt], bf[0][nt]);
                    mma16816(acc[mt][nt], af[0][mt], bf[1][nt]);
                    mma16816(acc[mt][nt], af[1][mt], bf[0][nt]);
                }
        }
        __syncthreads();
    }

    int gid = lane >> 2, tig = lane & 3;
    float* Sb = S + ((size_t)bh * NN_ + i0) * ldS + j0;
    #pragma unroll
    for (int mt = 0; mt < 4; mt++) {
        #pragma unroll
        for (int nt = 0; nt < 4; nt++) {
            int colb = wn + nt*8 + tig*2;
            bool v0 = (j0 + colb < Lk), v1 = (j0 + colb + 1 < Lk);
            #pragma unroll
            for (int half = 0; half < 2; half++) {
                int rl = wm + mt*16 + gid + half*8;
                float vx = v0 ? acc[mt][nt][half*2+0]*scale : -1e30f;
                float vy = v1 ? acc[mt][nt][half*2+1]*scale : -1e30f;
                *(float2*)(Sb + (size_t)rl * ldS + colb) = make_float2(vx, vy);
            }
        }
    }
}

// ================ tensor attention output: O = P @ V ========================
__global__ __launch_bounds__(256) void attn_o_mma(
    const float* __restrict__ P, int ldP, int kChunks,
    const float* __restrict__ V, int ldv, int vRows,
    float* __restrict__ O, int ldo)
{
    __shared__ __nv_bfloat16 sA[2][128][SPAD];   // P [hi/lo][m][k]
    __shared__ __nv_bfloat16 sB[2][64][SPAD];    // V^T [hi/lo][n][k]

    int bh = blockIdx.y, b = bh >> 4, h = bh & 15;
    int i0 = blockIdx.x * 128;
    const float* Pb = P + ((size_t)bh * NN_ + i0) * ldP;
    const float* Vb = V + (size_t)(b * vRows) * ldv + h * HDD;

    int tid = threadIdx.x;
    int wid = tid >> 5, lane = tid & 31;

    float acc[8][4];
    #pragma unroll
    for (int nt = 0; nt < 8; nt++)
        #pragma unroll
        for (int cc = 0; cc < 4; cc++) acc[nt][cc] = 0.f;

    uint32_t aBase[2], bBase[2];
    {
        int arow = wid*16 + (lane & 15);
        int acol = (lane >> 4) * 8;
        aBase[0] = smem_u32(&sA[0][arow][acol]);
        aBase[1] = smem_u32(&sA[1][arow][acol]);
        int brow = lane & 7;
        int bcol = ((lane >> 3) & 1) * 8;
        bBase[0] = smem_u32(&sB[0][brow][bcol]);
        bBase[1] = smem_u32(&sB[1][brow][bcol]);
    }

    int lr = tid >> 3;
    int lc = (tid & 7) * 4;

    for (int kt = 0; kt < kChunks; kt++) {
        int k0 = kt*32;
        // P chunk [128 x 32]
        #pragma unroll
        for (int i = 0; i < 4; i++) {
            int row = lr + i*32;
            float4 va = *(const float4*)(Pb + (size_t)row*ldP + k0 + lc);
            uint32_t h0, h1, l0, l1;
            split4(va, h0, h1, l0, l1);
            *(uint2*)&sA[0][row][lc] = make_uint2(h0, h1);
            *(uint2*)&sA[1][row][lc] = make_uint2(l0, l1);
        }
        // V chunk [32 x 64] -> transposed into sB [64][32]
        #pragma unroll
        for (int i = 0; i < 2; i++) {
            int lin = tid + i*256;
            int kr = lin >> 4;            // 0..31
            int nc = (lin & 15) * 4;      // 0..60
            float4 vv = *(const float4*)(Vb + (size_t)(k0 + kr)*ldv + nc);
            __nv_bfloat16 hh, ll;
            hh = __float2bfloat16_rn(vv.x); ll = __float2bfloat16_rn(vv.x - __bfloat162float(hh));
            sB[0][nc+0][kr] = hh; sB[1][nc+0][kr] = ll;
            hh = __float2bfloat16_rn(vv.y); ll = __float2bfloat16_rn(vv.y - __bfloat162float(hh));
            sB[0][nc+1][kr] = hh; sB[1][nc+1][kr] = ll;
            hh = __float2bfloat16_rn(vv.z); ll = __float2bfloat16_rn(vv.z - __bfloat162float(hh));
            sB[0][nc+2][kr] = hh; sB[1][nc+2][kr] = ll;
            hh = __float2bfloat16_rn(vv.w); ll = __float2bfloat16_rn(vv.w - __bfloat162float(hh));
            sB[0][nc+3][kr] = hh; sB[1][nc+3][kr] = ll;
        }
        __syncthreads();

        #pragma unroll
        for (int k16 = 0; k16 < 2; k16++) {
            uint32_t af[2][4], bf[2][8][2];
            #pragma unroll
            for (int p = 0; p < 2; p++) {
                ldsm_x4(af[p][0], af[p][1], af[p][2], af[p][3],
                        aBase[p] + (uint32_t)(k16*16) * 2);
                #pragma unroll
                for (int nt = 0; nt < 8; nt++)
                    ldsm_x2(bf[p][nt][0], bf[p][nt][1],
                            bBase[p] + (uint32_t)(nt*8*SPAD + k16*16) * 2);
            }
            #pragma unroll
            for (int nt = 0; nt < 8; nt++) {
                mma16816(acc[nt], af[0], bf[0][nt]);
                mma16816(acc[nt], af[0], bf[1][nt]);
                mma16816(acc[nt], af[1], bf[0][nt]);
            }
        }
        __syncthreads();
    }

    int gid = lane >> 2, tig = lane & 3;
    #pragma unroll
    for (int nt = 0; nt < 8; nt++) {
        int col = nt*8 + tig*2;
        #pragma unroll
        for (int half = 0; half < 2; half++) {
            int row = i0 + wid*16 + gid + half*8;
            *(float2*)(O + (size_t)(b * NN_ + row) * ldo + h * HDD + col) =
                make_float2(acc[nt][half*2+0], acc[nt][half*2+1]);
        }
    }
}

// ---------------- row softmax over ldS columns ------------------------------
__global__ __launch_bounds__(256) void softmax_kernel(float* __restrict__ S, int ldS)
{
    int row = blockIdx.x;
    int bh  = blockIdx.y;
    float* p = S + ((size_t)bh * NN_ + row) * ldS;
    int tid = threadIdx.x;
    __shared__ float red[8];

    float m = -1e30f;
    for (int i = tid; i < ldS; i += 256) m = fmaxf(m, p[i]);
    #pragma unroll
    for (int o = 16; o; o >>= 1) m = fmaxf(m, __shfl_xor_sync(0xffffffffu, m, o));
    if ((tid & 31) == 0) red[tid >> 5] = m;
    __syncthreads();
    float mm = red[0];
    #pragma unroll
    for (int i = 1; i < 8; i++) mm = fmaxf(mm, red[i]);
    __syncthreads();

    float s = 0.f;
    for (int i = tid; i < ldS; i += 256) {
        float e = expf(p[i] - mm);
        p[i] = e;
        s += e;
    }
    #pragma unroll
    for (int o = 16; o; o >>= 1) s += __shfl_xor_sync(0xffffffffu, s, o);
    if ((tid & 31) == 0) red[tid >> 5] = s;
    __syncthreads();
    float tot = 0.f;
    #pragma unroll
    for (int i = 0; i < 8; i++) tot += red[i];
    float inv = 1.0f / tot;
    for (int i = tid; i < ldS; i += 256) p[i] *= inv;
}

// ---------------- launch ----------------------------------------------------
extern "C" void kernel_launch(void* const* d_in, const int* in_sizes, int n_in,
                              void* d_out, int out_size)
{
    (void)in_sizes; (void)n_in; (void)out_size;
    const float* x     = (const float*)d_in[0];
    const float* c     = (const float*)d_in[1];
    const float* te    = (const float*)d_in[2];
    const float* W_ada = (const float*)d_in[3];
    const float* b_ada = (const float*)d_in[4];
    const float* W_qkv = (const float*)d_in[5];
    const float* b_qkv = (const float*)d_in[6];
    const float* W_proj= (const float*)d_in[7];
    const float* b_proj= (const float*)d_in[8];
    const float* W_ctx = (const float*)d_in[9];
    const float* b_ctx = (const float*)d_in[10];
    const float* W_q   = (const float*)d_in[11];
    const float* W_k   = (const float*)d_in[12];
    const float* W_v   = (const float*)d_in[13];
    const float* W_out = (const float*)d_in[14];
    const float* b_out = (const float*)d_in[15];
    const float* W_fc1 = (const float*)d_in[16];
    const float* b_fc1 = (const float*)d_in[17];
    const float* W_fc2 = (const float*)d_in[18];
    const float* b_fc2 = (const float*)d_in[19];
    float* out = (float*)d_out;

    float *mod, *hbuf, *qkv, *attn, *x1, *x2, *ctxb, *qb, *kb, *vb, *Sb, *hid;
    float *WtQKV, *WtPROJ, *WtQ, *WtK, *WtV, *WtOUT, *WtFC1, *WtFC2, *WtCTX;
    cudaGetSymbolAddress((void**)&mod,  g_mod);
    cudaGetSymbolAddress((void**)&hbuf, g_h);
    cudaGetSymbolAddress((void**)&qkv,  g_qkv);
    cudaGetSymbolAddress((void**)&attn, g_attn);
    cudaGetSymbolAddress((void**)&x1,   g_x1);
    cudaGetSymbolAddress((void**)&x2,   g_x2);
    cudaGetSymbolAddress((void**)&ctxb, g_ctx);
    cudaGetSymbolAddress((void**)&qb,   g_q);
    cudaGetSymbolAddress((void**)&kb,   g_k);
    cudaGetSymbolAddress((void**)&vb,   g_v);
    cudaGetSymbolAddress((void**)&Sb,   g_S);
    cudaGetSymbolAddress((void**)&hid,  g_hidden);
    cudaGetSymbolAddress((void**)&WtQKV,  g_Wt_qkv);
    cudaGetSymbolAddress((void**)&WtPROJ, g_Wt_proj);
    cudaGetSymbolAddress((void**)&WtQ,    g_Wt_q);
    cudaGetSymbolAddress((void**)&WtK,    g_Wt_k);
    cudaGetSymbolAddress((void**)&WtV,    g_Wt_v);
    cudaGetSymbolAddress((void**)&WtOUT,  g_Wt_out);
    cudaGetSymbolAddress((void**)&WtFC1,  g_Wt_fc1);
    cudaGetSymbolAddress((void**)&WtFC2,  g_Wt_fc2);
    cudaGetSymbolAddress((void**)&WtCTX,  g_Wt_ctx);

    const float scale = 0.125f;   // HD^-0.5
    dim3 tb(32, 8);

    // weight transposes (per-launch, deterministic)
    transpose_kernel<<<dim3(3072/32, 1024/32), tb>>>(W_qkv,  WtQKV,  1024, 3072);
    transpose_kernel<<<dim3(1024/32, 1024/32), tb>>>(W_proj, WtPROJ, 1024, 1024);
    transpose_kernel<<<dim3(1024/32, 1024/32), tb>>>(W_q,    WtQ,    1024, 1024);
    transpose_kernel<<<dim3(1024/32, 1024/32), tb>>>(W_k,    WtK,    1024, 1024);
    transpose_kernel<<<dim3(1024/32, 1024/32), tb>>>(W_v,    WtV,    1024, 1024);
    transpose_kernel<<<dim3(1024/32, 1024/32), tb>>>(W_out,  WtOUT,  1024, 1024);
    transpose_kernel<<<dim3(4096/32, 1024/32), tb>>>(W_fc1,  WtFC1,  1024, 4096);
    transpose_kernel<<<dim3(1024/32, 4096/32), tb>>>(W_fc2,  WtFC2,  4096, 1024);
    transpose_kernel<<<dim3(1024/32,  768/32), tb>>>(W_ctx,  WtCTX,   768, 1024);

    // adaLN modulation
    ada_kernel<<<24, 256>>>(c, W_ada, b_ada, mod);

    // ---- self-attention ----
    ln_mod_kernel<<<MTOK, 256>>>(x, mod, hbuf, 0);
    mgemm_kernel<true,false,false><<<dim3(24, 32), 256>>>(
        hbuf, WtQKV, b_qkv, nullptr, qkv, MTOK, 3*DD, DD);
    attn_s_mma<<<dim3(NN_/128, NN_/128, 64), 256>>>(
        qkv, 3*DD, NN_, qkv + DD, 3*DD, NN_, Sb, NN_, NN_, scale);
    softmax_kernel<<<dim3(NN_, 64), 256>>>(Sb, NN_);
    attn_o_mma<<<dim3(NN_/128, 64), 256>>>(
        Sb, NN_, NN_/32, qkv + 2*DD, 3*DD, NN_, attn, DD);
    mgemm_kernel<true,false,true><<<dim3(8, 32), 256>>>(
        attn, WtPROJ, b_proj, x, x1, MTOK, DD, DD);

    // ---- cross-attention ----
    ln_mod_kernel<<<MTOK, 256>>>(x1, mod, hbuf, 2);
    mgemm_kernel<true,false,false><<<dim3(8, 3), 256>>>(
        te, WtCTX, b_ctx, nullptr, ctxb, BB*TLL, DD, TDD);
    mgemm_kernel<false,false,false><<<dim3(8, 32), 256>>>(
        hbuf, WtQ, nullptr, nullptr, qb, MTOK, DD, DD);
    mgemm_kernel<false,false,false><<<dim3(8, 3), 256>>>(
        ctxb, WtK, nullptr, nullptr, kb, BB*TLL, DD, DD);
    mgemm_kernel<false,false,false><<<dim3(8, 3), 256>>>(
        ctxb, WtV, nullptr, nullptr, vb, BB*TLL, DD, DD);
    attn_s_mma<<<dim3(1, NN_/128, 64), 256>>>(
        qb, DD, NN_, kb, DD, TLL, Sb, 128, TLL, scale);
    softmax_kernel<<<dim3(NN_, 64), 256>>>(Sb, 128);
    attn_o_mma<<<dim3(NN_/128, 64), 256>>>(
        Sb, 128, 4, vb, DD, TLL, attn, DD);
    mgemm_kernel<true,false,true><<<dim3(8, 32), 256>>>(
        attn, WtOUT, b_out, x1, x2, MTOK, DD, DD);

    // ---- MLP ----
    ln_mod_kernel<<<MTOK, 256>>>(x2, mod, hbuf, 4);
    mgemm_kernel<true,true,false><<<dim3(32, 32), 256>>>(
        hbuf, WtFC1, b_fc1, nullptr, hid, MTOK, 4*DD, DD);
    mgemm_kernel<true,false,true><<<dim3(8, 32), 256>>>(
        hid, WtFC2, b_fc2, x2, out, MTOK, DD, 4*DD);
}

// round 16
// speedup vs baseline: 1.0437x; 1.0437x over previous
#include <cuda_runtime.h>
#include <cuda_bf16.h>
#include <math.h>
#include <stdint.h>

#define BB   4
#define NN_  1024
#define DD   1024
#define HH   16
#define HDD  64
#define TDD  768
#define TLL  77
#define MTOK (BB*NN_)       // 4096

// ---------------- scratch (zero-initialized device globals) ----------------
__device__ float g_mod[BB*6*DD];
__device__ float g_h[MTOK*DD];
__device__ float g_qkv[MTOK*3*DD];
__device__ float g_attn[MTOK*DD];
__device__ float g_x1[MTOK*DD];
__device__ float g_x2[MTOK*DD];
__device__ float g_ctx[512*DD];          // 308 valid rows, rest stays 0
__device__ float g_q[MTOK*DD];
__device__ float g_k[512*DD];            // pad rows stay 0
__device__ float g_v[512*DD];            // pad rows stay 0
__device__ float g_S[64ull*1024*1024];   // score scratch
__device__ float g_hidden[(size_t)MTOK*4*DD];

// transposed weights [N, K] row-major
__device__ float g_Wt_qkv [3072u*1024u];
__device__ float g_Wt_proj[1024u*1024u];
__device__ float g_Wt_q   [1024u*1024u];
__device__ float g_Wt_k   [1024u*1024u];
__device__ float g_Wt_v   [1024u*1024u];
__device__ float g_Wt_out [1024u*1024u];
__device__ float g_Wt_fc1 [4096u*1024u];
__device__ float g_Wt_fc2 [4096u*1024u];
__device__ float g_Wt_ctx [1024u*768u];

__device__ __forceinline__ float gelu_tanh(float x) {
    float inner = 0.7978845608028654f * (x + 0.044715f * x * x * x);
    return 0.5f * x * (1.0f + tanhf(inner));
}

__device__ __forceinline__ uint32_t smem_u32(const void* p) {
    uint32_t a;
    asm("{ .reg .u64 t; cvta.to.shared.u64 t, %1; cvt.u32.u64 %0, t; }"
        : "=r"(a) : "l"(p));
    return a;
}

// ---------------- weight transpose: out[n*K+k] = in[k*N+n] ------------------
__global__ __launch_bounds__(256) void transpose_kernel(
    const float* __restrict__ in, float* __restrict__ outp, int K, int N)
{
    __shared__ float t[32][33];
    int n0 = blockIdx.x * 32, k0 = blockIdx.y * 32;
    int x = threadIdx.x, y = threadIdx.y;   // block (32, 8)
    #pragma unroll
    for (int i = 0; i < 32; i += 8)
        t[y + i][x] = in[(size_t)(k0 + y + i) * N + n0 + x];
    __syncthreads();
    #pragma unroll
    for (int i = 0; i < 32; i += 8)
        outp[(size_t)(n0 + y + i) * K + k0 + x] = t[x][y + i];
}

// ---------------- adaLN: mod = silu(c) @ W_ada + b_ada  [4, 6144] ----------
__global__ __launch_bounds__(256) void ada_kernel(
    const float* __restrict__ c, const float* __restrict__ W,
    const float* __restrict__ bias, float* __restrict__ mod)
{
    __shared__ float sc[BB][DD];
    int tid = threadIdx.x;
    for (int i = tid; i < BB*DD; i += 256) {
        float v = c[i];
        sc[i >> 10][i & 1023] = v / (1.0f + expf(-v));
    }
    __syncthreads();
    int col = blockIdx.x * 256 + tid;
    float a0 = 0.f, a1 = 0.f, a2 = 0.f, a3 = 0.f;
    #pragma unroll 4
    for (int k = 0; k < DD; k++) {
        float w = W[(size_t)k * (6*DD) + col];
        a0 += w * sc[0][k];
        a1 += w * sc[1][k];
        a2 += w * sc[2][k];
        a3 += w * sc[3][k];
    }
    float bb = bias[col];
    mod[0*(size_t)(6*DD) + col] = a0 + bb;
    mod[1*(size_t)(6*DD) + col] = a1 + bb;
    mod[2*(size_t)(6*DD) + col] = a2 + bb;
    mod[3*(size_t)(6*DD) + col] = a3 + bb;
}

// ---------------- LayerNorm + modulate -------------------------------------
__global__ __launch_bounds__(256) void ln_mod_kernel(
    const float* __restrict__ X, const float* __restrict__ mod,
    float* __restrict__ Y, int shiftChunk)
{
    __shared__ float red[2][8];
    int row = blockIdx.x;
    int b = row >> 10;
    int tid = threadIdx.x;
    const float4* xr = (const float4*)(X + (size_t)row * DD);
    float4 xv = xr[tid];
    float s  = xv.x + xv.y + xv.z + xv.w;
    float ss = xv.x*xv.x + xv.y*xv.y + xv.z*xv.z + xv.w*xv.w;
    #pragma unroll
    for (int o = 16; o; o >>= 1) {
        s  += __shfl_xor_sync(0xffffffffu, s,  o);
        ss += __shfl_xor_sync(0xffffffffu, ss, o);
    }
    if ((tid & 31) == 0) { red[0][tid >> 5] = s; red[1][tid >> 5] = ss; }
    __syncthreads();
    float ts = 0.f, tss = 0.f;
    #pragma unroll
    for (int i = 0; i < 8; i++) { ts += red[0][i]; tss += red[1][i]; }
    float mean = ts * (1.0f / (float)DD);
    float var  = tss * (1.0f / (float)DD) - mean * mean;
    float rstd = rsqrtf(var + 1e-6f);
    const float4* shp = (const float4*)(mod + (size_t)b*6*DD + (size_t)shiftChunk*DD);
    const float4* scp = (const float4*)(mod + (size_t)b*6*DD + (size_t)(shiftChunk+1)*DD);
    float4 sh4 = shp[tid];
    float4 sc4 = scp[tid];
    float4 y;
    y.x = (xv.x - mean) * rstd * (1.0f + sc4.x) + sh4.x;
    y.y = (xv.y - mean) * rstd * (1.0f + sc4.y) + sh4.y;
    y.z = (xv.z - mean) * rstd * (1.0f + sc4.z) + sh4.z;
    y.w = (xv.w - mean) * rstd * (1.0f + sc4.w) + sh4.w;
    ((float4*)(Y + (size_t)row * DD))[tid] = y;
}

// ======================= mma.sync split-bf16 common =========================

__device__ __forceinline__ void ldsm_x4(
    uint32_t& r0, uint32_t& r1, uint32_t& r2, uint32_t& r3, uint32_t addr)
{
    asm volatile("ldmatrix.sync.aligned.m8n8.x4.shared.b16 {%0,%1,%2,%3}, [%4];"
                 : "=r"(r0), "=r"(r1), "=r"(r2), "=r"(r3) : "r"(addr));
}
__device__ __forceinline__ void ldsm_x2(uint32_t& r0, uint32_t& r1, uint32_t addr)
{
    asm volatile("ldmatrix.sync.aligned.m8n8.x2.shared.b16 {%0,%1}, [%2];"
                 : "=r"(r0), "=r"(r1) : "r"(addr));
}
__device__ __forceinline__ void mma16816(
    float* c, const uint32_t* a, const uint32_t* b)
{
    asm volatile(
        "mma.sync.aligned.m16n8k16.row.col.f32.bf16.bf16.f32 "
        "{%0,%1,%2,%3}, {%4,%5,%6,%7}, {%8,%9}, {%0,%1,%2,%3};"
        : "+f"(c[0]), "+f"(c[1]), "+f"(c[2]), "+f"(c[3])
        : "r"(a[0]), "r"(a[1]), "r"(a[2]), "r"(a[3]), "r"(b[0]), "r"(b[1]));
}

#define SPAD 40   // bf16 elements per smem row (32 data + 8 pad)

__device__ __forceinline__ void split4(float4 v, uint32_t& h0, uint32_t& h1,
                                       uint32_t& l0, uint32_t& l1)
{
    __nv_bfloat16 a = __float2bfloat16_rn(v.x);
    __nv_bfloat16 b = __float2bfloat16_rn(v.y);
    __nv_bfloat16 c = __float2bfloat16_rn(v.z);
    __nv_bfloat16 d = __float2bfloat16_rn(v.w);
    h0 = ((uint32_t)__bfloat16_as_ushort(b) << 16) | __bfloat16_as_ushort(a);
    h1 = ((uint32_t)__bfloat16_as_ushort(d) << 16) | __bfloat16_as_ushort(c);
    __nv_bfloat16 e = __float2bfloat16_rn(v.x - __bfloat162float(a));
    __nv_bfloat16 f = __float2bfloat16_rn(v.y - __bfloat162float(b));
    __nv_bfloat16 g = __float2bfloat16_rn(v.z - __bfloat162float(c));
    __nv_bfloat16 h = __float2bfloat16_rn(v.w - __bfloat162float(d));
    l0 = ((uint32_t)__bfloat16_as_ushort(f) << 16) | __bfloat16_as_ushort(e);
    l1 = ((uint32_t)__bfloat16_as_ushort(h) << 16) | __bfloat16_as_ushort(g);
}

// ======================= split-bf16 GEMM (linear layers) ====================
// (256, 2): 2 CTAs/SM (measured R13 win). Register prefetch of next K-chunk
// overlaps global-load latency with the mma compute phase (R14, noise-adjusted win).
template<bool HAS_BIAS, bool DO_GELU, bool HAS_RES>
__global__ __launch_bounds__(256, 2) void mgemm_kernel(
    const float* __restrict__ A, const float* __restrict__ Bt,
    const float* __restrict__ bias, const float* __restrict__ res,
    float* __restrict__ C, int M, int Nn, int K)
{
    __shared__ __nv_bfloat16 sA[2][128][SPAD];
    __shared__ __nv_bfloat16 sB[2][128][SPAD];

    int tid = threadIdx.x;
    int wid = tid >> 5, lane = tid & 31;
    int wm = (wid & 1) * 64;
    int wn = (wid >> 1) * 32;
    int m0 = blockIdx.y * 128;
    int n0 = blockIdx.x * 128;

    float acc[4][4][4];
    #pragma unroll
    for (int i = 0; i < 4; i++)
        #pragma unroll
        for (int j = 0; j < 4; j++)
            #pragma unroll
            for (int cc = 0; cc < 4; cc++) acc[i][j][cc] = 0.f;

    uint32_t aBase[2], bBase[2];
    {
        int arow = wm + (lane & 15);
        int acol = (lane >> 4) * 8;
        aBase[0] = smem_u32(&sA[0][arow][acol]);
        aBase[1] = smem_u32(&sA[1][arow][acol]);
        int brow = wn + (lane & 7);
        int bcol = ((lane >> 3) & 1) * 8;
        bBase[0] = smem_u32(&sB[0][brow][bcol]);
        bBase[1] = smem_u32(&sB[1][brow][bcol]);
    }

    int lr = tid >> 3;
    int lc = (tid & 7) * 4;

    int nkt = K >> 5;
    float4 pa[4], pb[4];
    // ---- prologue: load chunk 0 ----
    {
        const float* Ab = A + (size_t)m0 * K;
        const float* Bb = Bt + (size_t)n0 * K;
        #pragma unroll
        for (int i = 0; i < 4; i++) {
            int row = lr + i*32;
            pa[i] = (m0 + row < M) ? *(const float4*)(Ab + (size_t)row*K + lc)
                                   : make_float4(0.f, 0.f, 0.f, 0.f);
            pb[i] = *(const float4*)(Bb + (size_t)row*K + lc);
        }
    }

    for (int kt = 0; kt < nkt; kt++) {
        // ---- split + store current chunk ----
        #pragma unroll
        for (int i = 0; i < 4; i++) {
            int row = lr + i*32;
            uint32_t h0, h1, l0, l1;
            split4(pa[i], h0, h1, l0, l1);
            *(uint2*)&sA[0][row][lc] = make_uint2(h0, h1);
            *(uint2*)&sA[1][row][lc] = make_uint2(l0, l1);
            split4(pb[i], h0, h1, l0, l1);
            *(uint2*)&sB[0][row][lc] = make_uint2(h0, h1);
            *(uint2*)&sB[1][row][lc] = make_uint2(l0, l1);
        }
        __syncthreads();

        // ---- prefetch next chunk (LDGs overlap mma below) ----
        if (kt + 1 < nkt) {
            const float* Ab = A + (size_t)m0 * K + (kt+1)*32;
            const float* Bb = Bt + (size_t)n0 * K + (kt+1)*32;
            #pragma unroll
            for (int i = 0; i < 4; i++) {
                int row = lr + i*32;
                pa[i] = (m0 + row < M)
                        ? *(const float4*)(Ab + (size_t)row*K + lc)
                        : make_float4(0.f, 0.f, 0.f, 0.f);
                pb[i] = *(const float4*)(Bb + (size_t)row*K + lc);
            }
        }

        // ---- compute ----
        #pragma unroll
        for (int k16 = 0; k16 < 2; k16++) {
            uint32_t af[2][4][4], bf[2][4][2];
            #pragma unroll
            for (int p = 0; p < 2; p++) {
                #pragma unroll
                for (int mt = 0; mt < 4; mt++)
                    ldsm_x4(af[p][mt][0], af[p][mt][1], af[p][mt][2], af[p][mt][3],
                            aBase[p] + (uint32_t)(mt*16*SPAD + k16*16) * 2);
                #pragma unroll
                for (int nt = 0; nt < 4; nt++)
                    ldsm_x2(bf[p][nt][0], bf[p][nt][1],
                            bBase[p] + (uint32_t)(nt*8*SPAD + k16*16) * 2);
            }
            #pragma unroll
            for (int mt = 0; mt < 4; mt++)
                #pragma unroll
                for (int nt = 0; nt < 4; nt++) {
                    mma16816(acc[mt][nt], af[0][mt], bf[0][nt]);
                    mma16816(acc[mt][nt], af[0][mt], bf[1][nt]);
                    mma16816(acc[mt][nt], af[1][mt], bf[0][nt]);
                }
        }
        __syncthreads();
    }

    int gid = lane >> 2, tig = lane & 3;
    #pragma unroll
    for (int mt = 0; mt < 4; mt++) {
        #pragma unroll
        for (int nt = 0; nt < 4; nt++) {
            int col = n0 + wn + nt*8 + tig*2;
            float bx = 0.f, by = 0.f;
            if (HAS_BIAS) { bx = bias[col]; by = bias[col+1]; }
            #pragma unroll
            for (int half = 0; half < 2; half++) {
                int row = m0 + wm + mt*16 + gid + half*8;
                if (row < M) {
                    float vx = acc[mt][nt][half*2+0];
                    float vy = acc[mt][nt][half*2+1];
                    if (HAS_BIAS) { vx += bx; vy += by; }
                    if (DO_GELU)  { vx = gelu_tanh(vx); vy = gelu_tanh(vy); }
                    if (HAS_RES) {
                        float2 r2 = *(const float2*)(res + (size_t)row*Nn + col);
                        vx += r2.x; vy += r2.y;
                    }
                    *(float2*)(C + (size_t)row*Nn + col) = make_float2(vx, vy);
                }
            }
        }
    }
}

// ================= tensor attention scores: S = scale*Q@K^T =================
__global__ __launch_bounds__(256, 2) void attn_s_mma(
    const float* __restrict__ Q, int ldq, int qRows,
    const float* __restrict__ Kp, int ldk, int kRows,
    float* __restrict__ S, int ldS, int Lk, float scale)
{
    __shared__ __nv_bfloat16 sA[2][128][SPAD];
    __shared__ __nv_bfloat16 sB[2][128][SPAD];

    int bh = blockIdx.z, b = bh >> 4, h = bh & 15;
    int i0 = blockIdx.y * 128;
    int j0 = blockIdx.x * 128;
    const float* Qb = Q  + (size_t)(b * qRows + i0) * ldq + h * HDD;
    const float* Kb = Kp + (size_t)(b * kRows + j0) * ldk + h * HDD;

    int tid = threadIdx.x;
    int wid = tid >> 5, lane = tid & 31;
    int wm = (wid & 1) * 64;
    int wn = (wid >> 1) * 32;

    float acc[4][4][4];
    #pragma unroll
    for (int i = 0; i < 4; i++)
        #pragma unroll
        for (int j = 0; j < 4; j++)
            #pragma unroll
            for (int cc = 0; cc < 4; cc++) acc[i][j][cc] = 0.f;

    uint32_t aBase[2], bBase[2];
    {
        int arow = wm + (lane & 15);
        int acol = (lane >> 4) * 8;
        aBase[0] = smem_u32(&sA[0][arow][acol]);
        aBase[1] = smem_u32(&sA[1][arow][acol]);
        int brow = wn + (lane & 7);
        int bcol = ((lane >> 3) & 1) * 8;
        bBase[0] = smem_u32(&sB[0][brow][bcol]);
        bBase[1] = smem_u32(&sB[1][brow][bcol]);
    }

    int lr = tid >> 3;
    int lc = (tid & 7) * 4;

    #pragma unroll
    for (int kt = 0; kt < 2; kt++) {     // K = HDD = 64
        #pragma unroll
        for (int i = 0; i < 4; i++) {
            int row = lr + i*32;
            float4 va = *(const float4*)(Qb + (size_t)row*ldq + kt*32 + lc);
            uint32_t h0, h1, l0, l1;
            split4(va, h0, h1, l0, l1);
            *(uint2*)&sA[0][row][lc] = make_uint2(h0, h1);
            *(uint2*)&sA[1][row][lc] = make_uint2(l0, l1);
            float4 vb = *(const float4*)(Kb + (size_t)row*ldk + kt*32 + lc);
            split4(vb, h0, h1, l0, l1);
            *(uint2*)&sB[0][row][lc] = make_uint2(h0, h1);
            *(uint2*)&sB[1][row][lc] = make_uint2(l0, l1);
        }
        __syncthreads();

        #pragma unroll
        for (int k16 = 0; k16 < 2; k16++) {
            uint32_t af[2][4][4], bf[2][4][2];
            #pragma unroll
            for (int p = 0; p < 2; p++) {
                #pragma unroll
                for (int mt = 0; mt < 4; mt++)
                    ldsm_x4(af[p][mt][0], af[p][mt][1], af[p][mt][2], af[p][mt][3],
                            aBase[p] + (uint32_t)(mt*16*SPAD + k16*16) * 2);
                #pragma unroll
                for (int nt = 0; nt < 4; nt++)
                    ldsm_x2(bf[p][nt][0], bf[p][nt][1],
                            bBase[p] + (uint32_t)(nt*8*SPAD + k16*16) * 2);
            }
            #pragma unroll
            for (int mt = 0; mt < 4; mt++)
                #pragma unroll
                for (int nt = 0; nt < 4; nt++) {
                    mma16816(acc[mt][nt], af[0][mt], bf[0][nt]);
                    mma16816(acc[mt][nt], af[0][mt], bf[1][nt]);
                    mma16816(acc[mt][nt], af[1][mt], bf[0][nt]);
                }
        }
        __syncthreads();
    }

    int gid = lane >> 2, tig = lane & 3;
    float* Sb = S + ((size_t)bh * NN_ + i0) * ldS + j0;
    #pragma unroll
    for (int mt = 0; mt < 4; mt++) {
        #pragma unroll
        for (int nt = 0; nt < 4; nt++) {
            int colb = wn + nt*8 + tig*2;
            bool v0 = (j0 + colb < Lk), v1 = (j0 + colb + 1 < Lk);
            #pragma unroll
            for (int half = 0; half < 2; half++) {
                int rl = wm + mt*16 + gid + half*8;
                float vx = v0 ? acc[mt][nt][half*2+0]*scale : -1e30f;
                float vy = v1 ? acc[mt][nt][half*2+1]*scale : -1e30f;
                *(float2*)(Sb + (size_t)rl * ldS + colb) = make_float2(vx, vy);
            }
        }
    }
}

// ================ tensor attention output: O = P @ V ========================
__global__ __launch_bounds__(256, 2) void attn_o_mma(
    const float* __restrict__ P, int ldP, int kChunks,
    const float* __restrict__ V, int ldv, int vRows,
    float* __restrict__ O, int ldo)
{
    __shared__ __nv_bfloat16 sA[2][128][SPAD];   // P [hi/lo][m][k]
    __shared__ __nv_bfloat16 sB[2][64][SPAD];    // V^T [hi/lo][n][k]

    int bh = blockIdx.y, b = bh >> 4, h = bh & 15;
    int i0 = blockIdx.x * 128;
    const float* Pb = P + ((size_t)bh * NN_ + i0) * ldP;
    const float* Vb = V + (size_t)(b * vRows) * ldv + h * HDD;

    int tid = threadIdx.x;
    int wid = tid >> 5, lane = tid & 31;

    float acc[8][4];
    #pragma unroll
    for (int nt = 0; nt < 8; nt++)
        #pragma unroll
        for (int cc = 0; cc < 4; cc++) acc[nt][cc] = 0.f;

    uint32_t aBase[2], bBase[2];
    {
        int arow = wid*16 + (lane & 15);
        int acol = (lane >> 4) * 8;
        aBase[0] = smem_u32(&sA[0][arow][acol]);
        aBase[1] = smem_u32(&sA[1][arow][acol]);
        int brow = lane & 7;
        int bcol = ((lane >> 3) & 1) * 8;
        bBase[0] = smem_u32(&sB[0][brow][bcol]);
        bBase[1] = smem_u32(&sB[1][brow][bcol]);
    }

    int lr = tid >> 3;
    int lc = (tid & 7) * 4;

    for (int kt = 0; kt < kChunks; kt++) {
        int k0 = kt*32;
        // P chunk [128 x 32]
        #pragma unroll
        for (int i = 0; i < 4; i++) {
            int row = lr + i*32;
            float4 va = *(const float4*)(Pb + (size_t)row*ldP + k0 + lc);
            uint32_t h0, h1, l0, l1;
            split4(va, h0, h1, l0, l1);
            *(uint2*)&sA[0][row][lc] = make_uint2(h0, h1);
            *(uint2*)&sA[1][row][lc] = make_uint2(l0, l1);
        }
        // V chunk [32 x 64] -> transposed into sB [64][32]
        #pragma unroll
        for (int i = 0; i < 2; i++) {
            int lin = tid + i*256;
            int kr = lin >> 4;            // 0..31
            int nc = (lin & 15) * 4;      // 0..60
            float4 vv = *(const float4*)(Vb + (size_t)(k0 + kr)*ldv + nc);
            __nv_bfloat16 hh, ll;
            hh = __float2bfloat16_rn(vv.x); ll = __float2bfloat16_rn(vv.x - __bfloat162float(hh));
            sB[0][nc+0][kr] = hh; sB[1][nc+0][kr] = ll;
            hh = __float2bfloat16_rn(vv.y); ll = __float2bfloat16_rn(vv.y - __bfloat162float(hh));
            sB[0][nc+1][kr] = hh; sB[1][nc+1][kr] = ll;
            hh = __float2bfloat16_rn(vv.z); ll = __float2bfloat16_rn(vv.z - __bfloat162float(hh));
            sB[0][nc+2][kr] = hh; sB[1][nc+2][kr] = ll;
            hh = __float2bfloat16_rn(vv.w); ll = __float2bfloat16_rn(vv.w - __bfloat162float(hh));
            sB[0][nc+3][kr] = hh; sB[1][nc+3][kr] = ll;
        }
        __syncthreads();

        #pragma unroll
        for (int k16 = 0; k16 < 2; k16++) {
            uint32_t af[2][4], bf[2][8][2];
            #pragma unroll
            for (int p = 0; p < 2; p++) {
                ldsm_x4(af[p][0], af[p][1], af[p][2], af[p][3],
                        aBase[p] + (uint32_t)(k16*16) * 2);
                #pragma unroll
                for (int nt = 0; nt < 8; nt++)
                    ldsm_x2(bf[p][nt][0], bf[p][nt][1],
                            bBase[p] + (uint32_t)(nt*8*SPAD + k16*16) * 2);
            }
            #pragma unroll
            for (int nt = 0; nt < 8; nt++) {
                mma16816(acc[nt], af[0], bf[0][nt]);
                mma16816(acc[nt], af[0], bf[1][nt]);
                mma16816(acc[nt], af[1], bf[0][nt]);
            }
        }
        __syncthreads();
    }

    int gid = lane >> 2, tig = lane & 3;
    #pragma unroll
    for (int nt = 0; nt < 8; nt++) {
        int col = nt*8 + tig*2;
        #pragma unroll
        for (int half = 0; half < 2; half++) {
            int row = i0 + wid*16 + gid + half*8;
            *(float2*)(O + (size_t)(b * NN_ + row) * ldo + h * HDD + col) =
                make_float2(acc[nt][half*2+0], acc[nt][half*2+1]);
        }
    }
}

// ---------------- row softmax over ldS columns ------------------------------
__global__ __launch_bounds__(256) void softmax_kernel(float* __restrict__ S, int ldS)
{
    int row = blockIdx.x;
    int bh  = blockIdx.y;
    float* p = S + ((size_t)bh * NN_ + row) * ldS;
    int tid = threadIdx.x;
    __shared__ float red[8];

    float m = -1e30f;
    for (int i = tid; i < ldS; i += 256) m = fmaxf(m, p[i]);
    #pragma unroll
    for (int o = 16; o; o >>= 1) m = fmaxf(m, __shfl_xor_sync(0xffffffffu, m, o));
    if ((tid & 31) == 0) red[tid >> 5] = m;
    __syncthreads();
    float mm = red[0];
    #pragma unroll
    for (int i = 1; i < 8; i++) mm = fmaxf(mm, red[i]);
    __syncthreads();

    float s = 0.f;
    for (int i = tid; i < ldS; i += 256) {
        float e = expf(p[i] - mm);
        p[i] = e;
        s += e;
    }
    #pragma unroll
    for (int o = 16; o; o >>= 1) s += __shfl_xor_sync(0xffffffffu, s, o);
    if ((tid & 31) == 0) red[tid >> 5] = s;
    __syncthreads();
    float tot = 0.f;
    #pragma unroll
    for (int i = 0; i < 8; i++) tot += red[i];
    float inv = 1.0f / tot;
    for (int i = tid; i < ldS; i += 256) p[i] *= inv;
}

// ---------------- launch ----------------------------------------------------
extern "C" void kernel_launch(void* const* d_in, const int* in_sizes, int n_in,
                              void* d_out, int out_size)
{
    (void)in_sizes; (void)n_in; (void)out_size;
    const float* x     = (const float*)d_in[0];
    const float* c     = (const float*)d_in[1];
    const float* te    = (const float*)d_in[2];
    const float* W_ada = (const float*)d_in[3];
    const float* b_ada = (const float*)d_in[4];
    const float* W_qkv = (const float*)d_in[5];
    const float* b_qkv = (const float*)d_in[6];
    const float* W_proj= (const float*)d_in[7];
    const float* b_proj= (const float*)d_in[8];
    const float* W_ctx = (const float*)d_in[9];
    const float* b_ctx = (const float*)d_in[10];
    const float* W_q   = (const float*)d_in[11];
    const float* W_k   = (const float*)d_in[12];
    const float* W_v   = (const float*)d_in[13];
    const float* W_out = (const float*)d_in[14];
    const float* b_out = (const float*)d_in[15];
    const float* W_fc1 = (const float*)d_in[16];
    const float* b_fc1 = (const float*)d_in[17];
    const float* W_fc2 = (const float*)d_in[18];
    const float* b_fc2 = (const float*)d_in[19];
    float* out = (float*)d_out;

    float *mod, *hbuf, *qkv, *attn, *x1, *x2, *ctxb, *qb, *kb, *vb, *Sb, *hid;
    float *WtQKV, *WtPROJ, *WtQ, *WtK, *WtV, *WtOUT, *WtFC1, *WtFC2, *WtCTX;
    cudaGetSymbolAddress((void**)&mod,  g_mod);
    cudaGetSymbolAddress((void**)&hbuf, g_h);
    cudaGetSymbolAddress((void**)&qkv,  g_qkv);
    cudaGetSymbolAddress((void**)&attn, g_attn);
    cudaGetSymbolAddress((void**)&x1,   g_x1);
    cudaGetSymbolAddress((void**)&x2,   g_x2);
    cudaGetSymbolAddress((void**)&ctxb, g_ctx);
    cudaGetSymbolAddress((void**)&qb,   g_q);
    cudaGetSymbolAddress((void**)&kb,   g_k);
    cudaGetSymbolAddress((void**)&vb,   g_v);
    cudaGetSymbolAddress((void**)&Sb,   g_S);
    cudaGetSymbolAddress((void**)&hid,  g_hidden);
    cudaGetSymbolAddress((void**)&WtQKV,  g_Wt_qkv);
    cudaGetSymbolAddress((void**)&WtPROJ, g_Wt_proj);
    cudaGetSymbolAddress((void**)&WtQ,    g_Wt_q);
    cudaGetSymbolAddress((void**)&WtK,    g_Wt_k);
    cudaGetSymbolAddress((void**)&WtV,    g_Wt_v);
    cudaGetSymbolAddress((void**)&WtOUT,  g_Wt_out);
    cudaGetSymbolAddress((void**)&WtFC1,  g_Wt_fc1);
    cudaGetSymbolAddress((void**)&WtFC2,  g_Wt_fc2);
    cudaGetSymbolAddress((void**)&WtCTX,  g_Wt_ctx);

    const float scale = 0.125f;   // HD^-0.5
    dim3 tb(32, 8);

    // weight transposes (per-launch, deterministic)
    transpose_kernel<<<dim3(3072/32, 1024/32), tb>>>(W_qkv,  WtQKV,  1024, 3072);
    transpose_kernel<<<dim3(1024/32, 1024/32), tb>>>(W_proj, WtPROJ, 1024, 1024);
    transpose_kernel<<<dim3(1024/32, 1024/32), tb>>>(W_q,    WtQ,    1024, 1024);
    transpose_kernel<<<dim3(1024/32, 1024/32), tb>>>(W_k,    WtK,    1024, 1024);
    transpose_kernel<<<dim3(1024/32, 1024/32), tb>>>(W_v,    WtV,    1024, 1024);
    transpose_kernel<<<dim3(1024/32, 1024/32), tb>>>(W_out,  WtOUT,  1024, 1024);
    transpose_kernel<<<dim3(4096/32, 1024/32), tb>>>(W_fc1,  WtFC1,  1024, 4096);
    transpose_kernel<<<dim3(1024/32, 4096/32), tb>>>(W_fc2,  WtFC2,  4096, 1024);
    transpose_kernel<<<dim3(1024/32,  768/32), tb>>>(W_ctx,  WtCTX,   768, 1024);

    // adaLN modulation
    ada_kernel<<<24, 256>>>(c, W_ada, b_ada, mod);

    // ---- self-attention ----
    ln_mod_kernel<<<MTOK, 256>>>(x, mod, hbuf, 0);
    mgemm_kernel<true,false,false><<<dim3(24, 32), 256>>>(
        hbuf, WtQKV, b_qkv, nullptr, qkv, MTOK, 3*DD, DD);
    attn_s_mma<<<dim3(NN_/128, NN_/128, 64), 256>>>(
        qkv, 3*DD, NN_, qkv + DD, 3*DD, NN_, Sb, NN_, NN_, scale);
    softmax_kernel<<<dim3(NN_, 64), 256>>>(Sb, NN_);
    attn_o_mma<<<dim3(NN_/128, 64), 256>>>(
        Sb, NN_, NN_/32, qkv + 2*DD, 3*DD, NN_, attn, DD);
    mgemm_kernel<true,false,true><<<dim3(8, 32), 256>>>(
        attn, WtPROJ, b_proj, x, x1, MTOK, DD, DD);

    // ---- cross-attention ----
    ln_mod_kernel<<<MTOK, 256>>>(x1, mod, hbuf, 2);
    mgemm_kernel<true,false,false><<<dim3(8, 3), 256>>>(
        te, WtCTX, b_ctx, nullptr, ctxb, BB*TLL, DD, TDD);
    mgemm_kernel<false,false,false><<<dim3(8, 32), 256>>>(
        hbuf, WtQ, nullptr, nullptr, qb, MTOK, DD, DD);
    mgemm_kernel<false,false,false><<<dim3(8, 3), 256>>>(
        ctxb, WtK, nullptr, nullptr, kb, BB*TLL, DD, DD);
    mgemm_kernel<false,false,false><<<dim3(8, 3), 256>>>(
        ctxb, WtV, nullptr, nullptr, vb, BB*TLL, DD, DD);
    attn_s_mma<<<dim3(1, NN_/128, 64), 256>>>(
        qb, DD, NN_, kb, DD, TLL, Sb, 128, TLL, scale);
    softmax_kernel<<<dim3(NN_, 64), 256>>>(Sb, 128);
    attn_o_mma<<<dim3(NN_/128, 64), 256>>>(
        Sb, 128, 4, vb, DD, TLL, attn, DD);
    mgemm_kernel<true,false,true><<<dim3(8, 32), 256>>>(
        attn, WtOUT, b_out, x1, x2, MTOK, DD, DD);

    // ---- MLP ----
    ln_mod_kernel<<<MTOK, 256>>>(x2, mod, hbuf, 4);
    mgemm_kernel<true,true,false><<<dim3(32, 32), 256>>>(
        hbuf, WtFC1, b_fc1, nullptr, hid, MTOK, 4*DD, DD);
    mgemm_kernel<true,false,true><<<dim3(8, 32), 256>>>(
        hid, WtFC2, b_fc2, x2, out, MTOK, DD, 4*DD);
}